// round 4
// baseline (speedup 1.0000x reference)
#include <cuda_runtime.h>
#include <cstdint>

// ---------------- problem constants ----------------
#define IN_F    64
#define EDGE_F  16
#define OUT_F   64
#define K1      144          // 2*IN_F + EDGE_F, = 18 k-tiles of 8
#define TILE_M  128          // edges per CTA tile
#define A_STR   168          // A row stride (floats); 168 mod 32 == 8
#define H_STR   72           // H / W row stride (floats); 72 mod 32 == 8

// smem (floats):
//  W1s [144][72], W2s [64][72], As [128][168], Hs [128][72], B1s[64], B2s[64], Ds[128]
#define W1S_OFF  0
#define W2S_OFF  (W1S_OFF + K1*H_STR)            // 10368
#define AS_OFF   (W2S_OFF + 64*H_STR)            // 14976
#define HS_OFF   (AS_OFF + TILE_M*A_STR)         // 36480
#define B1S_OFF  (HS_OFF + TILE_M*H_STR)         // 45696
#define B2S_OFF  (B1S_OFF + 64)
#define DS_OFF   (B2S_OFF + 64)
#define SMEM_WORDS (DS_OFF + TILE_M)             // 45952 words
#define SMEM_BYTES (SMEM_WORDS * 4)              // 183808 B

// ---------------- helpers ----------------
__device__ __forceinline__ uint32_t f2tf32(float f) {
    uint32_t r;
    asm("cvt.rna.tf32.f32 %0, %1;" : "=r"(r) : "f"(f));
    return r;
}

__device__ __forceinline__ void mma_tf32(float c[4],
                                         uint32_t a0, uint32_t a1, uint32_t a2, uint32_t a3,
                                         uint32_t b0, uint32_t b1) {
    asm volatile(
        "mma.sync.aligned.m16n8k8.row.col.f32.tf32.tf32.f32 "
        "{%0,%1,%2,%3}, {%4,%5,%6,%7}, {%8,%9}, {%0,%1,%2,%3};"
        : "+f"(c[0]), "+f"(c[1]), "+f"(c[2]), "+f"(c[3])
        : "r"(a0), "r"(a1), "r"(a2), "r"(a3), "r"(b0), "r"(b1));
}

__device__ __forceinline__ void red_add_v4(float* p, float a, float b, float c, float d) {
    asm volatile("red.global.add.v4.f32 [%0], {%1, %2, %3, %4};"
        :: "l"(p), "f"(a), "f"(b), "f"(c), "f"(d) : "memory");
}

__device__ __forceinline__ void sts_tf32x4(uint32_t* dst, float4 v) {
    uint4 u;
    u.x = f2tf32(v.x); u.y = f2tf32(v.y); u.z = f2tf32(v.z); u.w = f2tf32(v.w);
    *reinterpret_cast<uint4*>(dst) = u;
}

// ---------------- zero-init output ----------------
__global__ void ec_zero_kernel(float4* out, int n4) {
    int i = blockIdx.x * blockDim.x + threadIdx.x;
    if (i < n4) out[i] = make_float4(0.f, 0.f, 0.f, 0.f);
}

// ---------------- main persistent kernel ----------------
extern "C" __global__ void __launch_bounds__(256, 1)
ec_main_kernel(const float* __restrict__ x, const int* __restrict__ ei,
               const float* __restrict__ ea,
               const float* __restrict__ W1, const float* __restrict__ b1,
               const float* __restrict__ W2, const float* __restrict__ b2,
               float* __restrict__ out, int E, int ntiles)
{
    extern __shared__ float smem[];
    uint32_t* W1u = reinterpret_cast<uint32_t*>(smem + W1S_OFF);
    uint32_t* W2u = reinterpret_cast<uint32_t*>(smem + W2S_OFF);
    uint32_t* Au  = reinterpret_cast<uint32_t*>(smem + AS_OFF);
    uint32_t* Hu  = reinterpret_cast<uint32_t*>(smem + HS_OFF);
    float*    Hf  = smem + HS_OFF;
    float*    B1s = smem + B1S_OFF;
    float*    B2s = smem + B2S_OFF;
    int*      Ds  = reinterpret_cast<int*>(smem + DS_OFF);

    const int tid  = threadIdx.x;
    const int wid  = tid >> 5;
    const int lane = tid & 31;
    const int g    = lane >> 2;      // groupID 0..7
    const int tg   = lane & 3;       // thread-in-group 0..3
    const int rowbase = wid * 16;    // this warp's 16-row M chunk
    const int row  = tid & 127;      // gather row
    const int half = tid >> 7;       // gather half

    // ---- one-time weight/bias fill (tf32) ----
    for (int idx = tid; idx < K1 * 64; idx += 256) {
        int k = idx >> 6, n = idx & 63;
        W1u[k * H_STR + n] = f2tf32(W1[idx]);
    }
    for (int idx = tid; idx < 64 * 64; idx += 256) {
        int k = idx >> 6, n = idx & 63;
        W2u[k * H_STR + n] = f2tf32(W2[idx]);
    }
    if (tid < 64) { B1s[tid] = b1[tid]; B2s[tid] = b2[tid]; }
    __syncthreads();

    for (int tile = blockIdx.x; tile < ntiles; tile += gridDim.x) {
        const int e = tile * TILE_M + row;
        const bool valid = (e < E);

        // ---- gather A = [x[src] | x[dst] | edge_attr] as tf32 (edge_index is int32) ----
        if (half == 0) {
            if (valid) {
                int src = ei[e];
                const float4* xs = reinterpret_cast<const float4*>(x + (size_t)src * 64);
                #pragma unroll
                for (int i = 0; i < 16; i++)
                    sts_tf32x4(Au + row * A_STR + i * 4, __ldg(xs + i));
            }
        } else {
            if (valid) {
                int dst = ei[E + e];
                Ds[row] = dst;
                const float4* xd = reinterpret_cast<const float4*>(x + (size_t)dst * 64);
                #pragma unroll
                for (int i = 0; i < 16; i++)
                    sts_tf32x4(Au + row * A_STR + 64 + i * 4, __ldg(xd + i));
                const float4* eap = reinterpret_cast<const float4*>(ea + (size_t)e * 16);
                #pragma unroll
                for (int i = 0; i < 4; i++)
                    sts_tf32x4(Au + row * A_STR + 128 + i * 4, __ldg(eap + i));
            }
        }
        __syncthreads();

        // ---- layer 1: acc[128x64] = A[128x144] @ W1[144x64] ----
        float acc[8][4];
        #pragma unroll
        for (int nt = 0; nt < 8; nt++)
            acc[nt][0] = acc[nt][1] = acc[nt][2] = acc[nt][3] = 0.f;

        const uint32_t* arow0 = Au + (rowbase + g) * A_STR;
        const uint32_t* arow1 = Au + (rowbase + g + 8) * A_STR;
        #pragma unroll
        for (int kt = 0; kt < 18; kt++) {
            const int k0 = kt * 8;
            uint32_t a0 = arow0[k0 + tg];
            uint32_t a1 = arow1[k0 + tg];
            uint32_t a2 = arow0[k0 + tg + 4];
            uint32_t a3 = arow1[k0 + tg + 4];
            #pragma unroll
            for (int nt = 0; nt < 8; nt++) {
                uint32_t b0 = W1u[(k0 + tg) * H_STR + nt * 8 + g];
                uint32_t b1r = W1u[(k0 + tg + 4) * H_STR + nt * 8 + g];
                mma_tf32(acc[nt], a0, a1, a2, a3, b0, b1r);
            }
        }

        // ---- epilogue 1: bias + relu -> H (tf32). Fragment rows are warp-local. ----
        #pragma unroll
        for (int nt = 0; nt < 8; nt++) {
            int col = nt * 8 + tg * 2;
            float ba = B1s[col], bb = B1s[col + 1];
            uint2 lo, hi;
            lo.x = f2tf32(fmaxf(acc[nt][0] + ba, 0.f));
            lo.y = f2tf32(fmaxf(acc[nt][1] + bb, 0.f));
            hi.x = f2tf32(fmaxf(acc[nt][2] + ba, 0.f));
            hi.y = f2tf32(fmaxf(acc[nt][3] + bb, 0.f));
            *reinterpret_cast<uint2*>(Hu + (rowbase + g) * H_STR + col)     = lo;
            *reinterpret_cast<uint2*>(Hu + (rowbase + g + 8) * H_STR + col) = hi;
        }
        __syncwarp();

        // ---- layer 2: acc2[128x64] = H[128x64] @ W2[64x64] ----
        float acc2[8][4];
        #pragma unroll
        for (int nt = 0; nt < 8; nt++)
            acc2[nt][0] = acc2[nt][1] = acc2[nt][2] = acc2[nt][3] = 0.f;

        const uint32_t* hrow0 = Hu + (rowbase + g) * H_STR;
        const uint32_t* hrow1 = Hu + (rowbase + g + 8) * H_STR;
        #pragma unroll
        for (int kt = 0; kt < 8; kt++) {
            const int k0 = kt * 8;
            uint32_t a0 = hrow0[k0 + tg];
            uint32_t a1 = hrow1[k0 + tg];
            uint32_t a2 = hrow0[k0 + tg + 4];
            uint32_t a3 = hrow1[k0 + tg + 4];
            #pragma unroll
            for (int nt = 0; nt < 8; nt++) {
                uint32_t b0 = W2u[(k0 + tg) * H_STR + nt * 8 + g];
                uint32_t b1r = W2u[(k0 + tg + 4) * H_STR + nt * 8 + g];
                mma_tf32(acc2[nt], a0, a1, a2, a3, b0, b1r);
            }
        }
        __syncwarp();   // all H reads done before staging overwrites H

        // ---- epilogue 2: stage raw fp32 result into H buffer ----
        #pragma unroll
        for (int nt = 0; nt < 8; nt++) {
            int col = nt * 8 + tg * 2;
            float2 lo = make_float2(acc2[nt][0], acc2[nt][1]);
            float2 hi = make_float2(acc2[nt][2], acc2[nt][3]);
            *reinterpret_cast<float2*>(Hf + (rowbase + g) * H_STR + col)     = lo;
            *reinterpret_cast<float2*>(Hf + (rowbase + g + 8) * H_STR + col) = hi;
        }
        __syncthreads();

        // ---- scatter: bias + red.global.add.v4 ----
        #pragma unroll
        for (int i = 0; i < 8; i++) {
            int q = tid + i * 256;            // 0..2047 quads
            int r = q >> 4;
            int col = (q & 15) * 4;
            int ee = tile * TILE_M + r;
            if (ee < E) {
                float4 v = *reinterpret_cast<const float4*>(Hf + r * H_STR + col);
                float4 bv = *reinterpret_cast<const float4*>(B2s + col);
                float* op = out + (size_t)Ds[r] * 64 + col;
                red_add_v4(op, v.x + bv.x, v.y + bv.y, v.z + bv.z, v.w + bv.w);
            }
        }
        __syncthreads();   // protect A/H before next tile's writes
    }
}

// ---------------- launch ----------------
extern "C" void kernel_launch(void* const* d_in, const int* in_sizes, int n_in,
                              void* d_out, int out_size) {
    const float* x  = (const float*)d_in[0];
    const int*   ei = (const int*)d_in[1];      // JAX x64-disabled: int64 -> int32
    const float* ea = (const float*)d_in[2];
    const float* W1 = (const float*)d_in[3];
    const float* b1 = (const float*)d_in[4];
    const float* W2 = (const float*)d_in[5];
    const float* b2 = (const float*)d_in[6];
    float* out = (float*)d_out;

    int E = in_sizes[1] / 2;          // edge_index is (2, E)
    int ntiles = (E + TILE_M - 1) / TILE_M;

    int n4 = out_size / 4;
    ec_zero_kernel<<<(n4 + 255) / 256, 256>>>((float4*)out, n4);

    cudaFuncSetAttribute(ec_main_kernel, cudaFuncAttributeMaxDynamicSharedMemorySize, SMEM_BYTES);
    int sms = 148;
    cudaDeviceGetAttribute(&sms, cudaDevAttrMultiProcessorCount, 0);
    int grid = ntiles < sms ? ntiles : sms;

    ec_main_kernel<<<grid, 256, SMEM_BYTES>>>(x, ei, ea, W1, b1, W2, b2, out, E, ntiles);
}

// round 5
// speedup vs baseline: 1.1622x; 1.1622x over previous
#include <cuda_runtime.h>
#include <cstdint>

// ---------------- constants ----------------
#define TILE_M 128
#define A_STR  160                         // words per A row; XOR-swizzled
#define ASZ    (TILE_M * A_STR)            // 20480 words per A buffer

// smem word offsets
#define W1F_OFF 0                          // 18*8*32 uint2 = 9216 words
#define W2F_OFF 9216                       // 8*8*32 uint2  = 4096 words
#define B1S_OFF 13312                      // 64
#define B2S_OFF 13376                      // 64
#define DS_OFF  13440                      // 2*128 ints
#define A0_OFF  13824                      // 2 x 20480 words (A double buffer; H reuses)
#define SMEM_WORDS (A0_OFF + 2 * ASZ)      // 54784 words
#define SMEM_BYTES (SMEM_WORDS * 4)        // 219136 bytes

// ---------------- helpers ----------------
__device__ __forceinline__ uint32_t f2tf32(float f) {
    uint32_t r;
    asm("cvt.rna.tf32.f32 %0, %1;" : "=r"(r) : "f"(f));
    return r;
}

__device__ __forceinline__ void mma_tf32(float c[4],
                                         uint32_t a0, uint32_t a1, uint32_t a2, uint32_t a3,
                                         uint32_t b0, uint32_t b1) {
    asm volatile(
        "mma.sync.aligned.m16n8k8.row.col.f32.tf32.tf32.f32 "
        "{%0,%1,%2,%3}, {%4,%5,%6,%7}, {%8,%9}, {%0,%1,%2,%3};"
        : "+f"(c[0]), "+f"(c[1]), "+f"(c[2]), "+f"(c[3])
        : "r"(a0), "r"(a1), "r"(a2), "r"(a3), "r"(b0), "r"(b1));
}

__device__ __forceinline__ void red_add_v2(float* p, float a, float b) {
    asm volatile("red.global.add.v2.f32 [%0], {%1, %2};"
        :: "l"(p), "f"(a), "f"(b) : "memory");
}

__device__ __forceinline__ void sts_tf32x4(uint32_t* dst, float4 v) {
    uint4 u;
    u.x = f2tf32(v.x); u.y = f2tf32(v.y); u.z = f2tf32(v.z); u.w = f2tf32(v.w);
    *reinterpret_cast<uint4*>(dst) = u;
}

#define BAR_SYNC(id, cnt)   asm volatile("bar.sync %0, %1;"   :: "r"(id), "r"(cnt) : "memory")
#define BAR_ARRIVE(id, cnt) asm volatile("bar.arrive %0, %1;" :: "r"(id), "r"(cnt) : "memory")

// ---------------- zero-init output ----------------
__global__ void ec_zero_kernel(float4* out, int n4) {
    int i = blockIdx.x * blockDim.x + threadIdx.x;
    if (i < n4) out[i] = make_float4(0.f, 0.f, 0.f, 0.f);
}

// ---------------- main persistent kernel ----------------
extern "C" __global__ void __launch_bounds__(256, 1)
ec_main_kernel(const float* __restrict__ x, const int* __restrict__ ei,
               const float* __restrict__ ea,
               const float* __restrict__ W1, const float* __restrict__ b1,
               const float* __restrict__ W2, const float* __restrict__ b2,
               float* __restrict__ out, int E, int ntiles)
{
    extern __shared__ __align__(16) float smem[];
    uint32_t* W1F = reinterpret_cast<uint32_t*>(smem + W1F_OFF);
    uint32_t* W2F = reinterpret_cast<uint32_t*>(smem + W2F_OFF);
    float*    B1s = smem + B1S_OFF;
    float*    B2s = smem + B2S_OFF;
    int*      Dsm = reinterpret_cast<int*>(smem + DS_OFF);

    const int tid  = threadIdx.x;
    const int lane = tid & 31;
    const int g    = lane >> 2;       // 0..7
    const int tg   = lane & 3;        // 0..3

    // ---- one-time weight fill: fragment-major tf32 ----
    // W1F[kt][nt][lane] = {W1[8kt+tg][8nt+g], W1[8kt+tg+4][8nt+g]}
    for (int idx = tid; idx < 18 * 8 * 32; idx += 256) {
        int l = idx & 31, nt = (idx >> 5) & 7, kt = idx >> 8;
        int gg = l >> 2, tt = l & 3;
        W1F[idx * 2]     = f2tf32(W1[(8 * kt + tt) * 64 + 8 * nt + gg]);
        W1F[idx * 2 + 1] = f2tf32(W1[(8 * kt + tt + 4) * 64 + 8 * nt + gg]);
    }
    for (int idx = tid; idx < 8 * 8 * 32; idx += 256) {
        int l = idx & 31, nt = (idx >> 5) & 7, kt = idx >> 8;
        int gg = l >> 2, tt = l & 3;
        W2F[idx * 2]     = f2tf32(W2[(8 * kt + tt) * 64 + 8 * nt + gg]);
        W2F[idx * 2 + 1] = f2tf32(W2[(8 * kt + tt + 4) * 64 + 8 * nt + gg]);
    }
    if (tid < 64) { B1s[tid] = b1[tid]; B2s[tid] = b2[tid]; }
    __syncthreads();

    if (tid < 128) {
        // ================= CONSUMER (warps 0-3): compute M=32 each =================
        const int wid = tid >> 5;
        const int rb  = wid * 32;
        const int swz = 4 * g;

        float b1c[8][2], b2c[8][2];
        #pragma unroll
        for (int nt = 0; nt < 8; nt++) {
            int col = nt * 8 + 2 * tg;
            b1c[nt][0] = B1s[col]; b1c[nt][1] = B1s[col + 1];
            b2c[nt][0] = B2s[col]; b2c[nt][1] = B2s[col + 1];
        }

        int it = 0;
        for (int t = blockIdx.x; t < ntiles; t += gridDim.x, it++) {
            const int s = it & 1;
            BAR_SYNC(1 + s, 256);                      // wait A[s] full

            const uint32_t* Ab = reinterpret_cast<const uint32_t*>(smem + A0_OFF + s * ASZ);

            int dstr[4];
            #pragma unroll
            for (int j = 0; j < 4; j++) dstr[j] = Dsm[s * 128 + rb + 8 * j + g];

            // ---- layer 1: acc = A[128x144] @ W1 ----
            float acc[2][8][4];
            #pragma unroll
            for (int ch = 0; ch < 2; ch++)
                #pragma unroll
                for (int nt = 0; nt < 8; nt++)
                    acc[ch][nt][0] = acc[ch][nt][1] = acc[ch][nt][2] = acc[ch][nt][3] = 0.f;

            #pragma unroll
            for (int kt = 0; kt < 18; kt++) {
                const int k0 = kt * 8;
                uint32_t af[2][4];
                #pragma unroll
                for (int ch = 0; ch < 2; ch++) {
                    const int R0 = rb + 16 * ch + g;
                    af[ch][0] = Ab[R0 * A_STR + ((k0 + tg) ^ swz)];
                    af[ch][1] = Ab[(R0 + 8) * A_STR + ((k0 + tg) ^ swz)];
                    af[ch][2] = Ab[R0 * A_STR + ((k0 + tg + 4) ^ swz)];
                    af[ch][3] = Ab[(R0 + 8) * A_STR + ((k0 + tg + 4) ^ swz)];
                }
                #pragma unroll
                for (int nt = 0; nt < 8; nt++) {
                    uint2 b = *reinterpret_cast<const uint2*>(W1F + ((kt * 8 + nt) * 64 + lane * 2));
                    mma_tf32(acc[0][nt], af[0][0], af[0][1], af[0][2], af[0][3], b.x, b.y);
                    mma_tf32(acc[1][nt], af[1][0], af[1][1], af[1][2], af[1][3], b.x, b.y);
                }
            }

            BAR_SYNC(5, 128);                          // all layer-1 A reads done before H overwrite

            // ---- epilogue 1: bias + relu -> H (tf32), staged inside A[s] ----
            uint32_t* Hb = reinterpret_cast<uint32_t*>(smem + A0_OFF + s * ASZ);
            #pragma unroll
            for (int ch = 0; ch < 2; ch++) {
                const int R0 = rb + 16 * ch + g;
                #pragma unroll
                for (int nt = 0; nt < 8; nt++) {
                    const int col = nt * 8 + 2 * tg;
                    uint2 lo, hi;
                    lo.x = f2tf32(fmaxf(acc[ch][nt][0] + b1c[nt][0], 0.f));
                    lo.y = f2tf32(fmaxf(acc[ch][nt][1] + b1c[nt][1], 0.f));
                    hi.x = f2tf32(fmaxf(acc[ch][nt][2] + b1c[nt][0], 0.f));
                    hi.y = f2tf32(fmaxf(acc[ch][nt][3] + b1c[nt][1], 0.f));
                    *reinterpret_cast<uint2*>(Hb + R0 * 64 + (col ^ swz))       = lo;
                    *reinterpret_cast<uint2*>(Hb + (R0 + 8) * 64 + (col ^ swz)) = hi;
                }
            }
            __syncwarp();

            // ---- layer 2: acc = H[128x64] @ W2 ----
            #pragma unroll
            for (int ch = 0; ch < 2; ch++)
                #pragma unroll
                for (int nt = 0; nt < 8; nt++)
                    acc[ch][nt][0] = acc[ch][nt][1] = acc[ch][nt][2] = acc[ch][nt][3] = 0.f;

            #pragma unroll
            for (int kt = 0; kt < 8; kt++) {
                const int k0 = kt * 8;
                uint32_t af[2][4];
                #pragma unroll
                for (int ch = 0; ch < 2; ch++) {
                    const int R0 = rb + 16 * ch + g;
                    af[ch][0] = Hb[R0 * 64 + ((k0 + tg) ^ swz)];
                    af[ch][1] = Hb[(R0 + 8) * 64 + ((k0 + tg) ^ swz)];
                    af[ch][2] = Hb[R0 * 64 + ((k0 + tg + 4) ^ swz)];
                    af[ch][3] = Hb[(R0 + 8) * 64 + ((k0 + tg + 4) ^ swz)];
                }
                #pragma unroll
                for (int nt = 0; nt < 8; nt++) {
                    uint2 b = *reinterpret_cast<const uint2*>(W2F + ((kt * 8 + nt) * 64 + lane * 2));
                    mma_tf32(acc[0][nt], af[0][0], af[0][1], af[0][2], af[0][3], b.x, b.y);
                    mma_tf32(acc[1][nt], af[1][0], af[1][1], af[1][2], af[1][3], b.x, b.y);
                }
            }

            BAR_ARRIVE(3 + s, 256);                    // release A[s] (H reads done)

            // ---- scatter: bias + red.global.add.v2 straight from fragments ----
            const int base_e = t * TILE_M;
            #pragma unroll
            for (int ch = 0; ch < 2; ch++) {
                const int R0 = rb + 16 * ch + g;
                const bool v0 = (base_e + R0) < E;
                const bool v1 = (base_e + R0 + 8) < E;
                #pragma unroll
                for (int nt = 0; nt < 8; nt++) {
                    const int col = nt * 8 + 2 * tg;
                    if (v0) {
                        float* p0 = out + (size_t)dstr[2 * ch] * 64 + col;
                        red_add_v2(p0, acc[ch][nt][0] + b2c[nt][0], acc[ch][nt][1] + b2c[nt][1]);
                    }
                    if (v1) {
                        float* p1 = out + (size_t)dstr[2 * ch + 1] * 64 + col;
                        red_add_v2(p1, acc[ch][nt][2] + b2c[nt][0], acc[ch][nt][3] + b2c[nt][1]);
                    }
                }
            }
        }
    } else {
        // ================= PRODUCER (warps 4-7): gather next tile =================
        const int r = tid - 128;                       // 0..127, one edge row each
        const int sw = 4 * (r & 7);

        int it = 0;
        for (int t = blockIdx.x; t < ntiles; t += gridDim.x, it++) {
            const int s = it & 1;
            if (it >= 2) BAR_SYNC(3 + s, 256);         // wait A[s] empty

            uint32_t* Ab = reinterpret_cast<uint32_t*>(smem + A0_OFF + s * ASZ);
            const int e = t * TILE_M + r;
            if (e < E) {
                const int src = ei[e];
                const int dst = ei[E + e];
                Dsm[s * 128 + r] = dst;
                uint32_t* arow = Ab + r * A_STR;
                const float4* xs = reinterpret_cast<const float4*>(x + (size_t)src * 64);
                const float4* xd = reinterpret_cast<const float4*>(x + (size_t)dst * 64);
                const float4* ep = reinterpret_cast<const float4*>(ea + (size_t)e * 16);
                #pragma unroll
                for (int q = 0; q < 16; q++) sts_tf32x4(arow + ((4 * q) ^ sw), __ldg(xs + q));
                #pragma unroll
                for (int q = 0; q < 16; q++) sts_tf32x4(arow + ((64 + 4 * q) ^ sw), __ldg(xd + q));
                #pragma unroll
                for (int q = 0; q < 4; q++)  sts_tf32x4(arow + ((128 + 4 * q) ^ sw), __ldg(ep + q));
            }
            BAR_ARRIVE(1 + s, 256);                    // mark A[s] full
        }
    }
}

// ---------------- launch ----------------
extern "C" void kernel_launch(void* const* d_in, const int* in_sizes, int n_in,
                              void* d_out, int out_size) {
    const float* x  = (const float*)d_in[0];
    const int*   ei = (const int*)d_in[1];      // JAX x64-disabled: edge_index is int32
    const float* ea = (const float*)d_in[2];
    const float* W1 = (const float*)d_in[3];
    const float* b1 = (const float*)d_in[4];
    const float* W2 = (const float*)d_in[5];
    const float* b2 = (const float*)d_in[6];
    float* out = (float*)d_out;

    int E = in_sizes[1] / 2;
    int ntiles = (E + TILE_M - 1) / TILE_M;

    int n4 = out_size / 4;
    ec_zero_kernel<<<(n4 + 255) / 256, 256>>>((float4*)out, n4);

    cudaFuncSetAttribute(ec_main_kernel, cudaFuncAttributeMaxDynamicSharedMemorySize, SMEM_BYTES);
    int sms = 148;
    cudaDeviceGetAttribute(&sms, cudaDevAttrMultiProcessorCount, 0);
    int grid = ntiles < sms ? ntiles : sms;

    ec_main_kernel<<<grid, 256, SMEM_BYTES>>>(x, ei, ea, W1, b1, W2, b2, out, E, ntiles);
}

// round 6
// speedup vs baseline: 2.5328x; 2.1794x over previous
#include <cuda_runtime.h>
#include <cstdint>

#define NN 50000
#define NE 800000

// scratch (static __device__ per allocation rules)
__device__ float g_nm[(size_t)NN * 128];     // [n][0:64]=x@W1a+b1 , [n][64:128]=x@W1b
__device__ float g_hsum[(size_t)NN * 64];    // per-node sum of relu(h)
__device__ float g_deg[NN];                  // per-node edge count

// ---------------- helpers ----------------
__device__ __forceinline__ uint32_t f2tf32(float f) {
    uint32_t r;
    asm("cvt.rna.tf32.f32 %0, %1;" : "=r"(r) : "f"(f));
    return r;
}
__device__ __forceinline__ void mma_tf32(float c[4],
                                         uint32_t a0, uint32_t a1, uint32_t a2, uint32_t a3,
                                         uint32_t b0, uint32_t b1) {
    asm volatile(
        "mma.sync.aligned.m16n8k8.row.col.f32.tf32.tf32.f32 "
        "{%0,%1,%2,%3}, {%4,%5,%6,%7}, {%8,%9}, {%0,%1,%2,%3};"
        : "+f"(c[0]), "+f"(c[1]), "+f"(c[2]), "+f"(c[3])
        : "r"(a0), "r"(a1), "r"(a2), "r"(a3), "r"(b0), "r"(b1));
}
__device__ __forceinline__ void red_add_v4(float* p, float a, float b, float c, float d) {
    asm volatile("red.global.add.v4.f32 [%0], {%1, %2, %3, %4};"
        :: "l"(p), "f"(a), "f"(b), "f"(c), "f"(d) : "memory");
}
__device__ __forceinline__ void red_add_f32(float* p, float v) {
    asm volatile("red.global.add.f32 [%0], %1;" :: "l"(p), "f"(v) : "memory");
}

// ---------------- zero scratch ----------------
__global__ void zero_kernel() {
    int i = blockIdx.x * blockDim.x + threadIdx.x;
    float4 z = make_float4(0.f, 0.f, 0.f, 0.f);
    if (i < NN * 16) reinterpret_cast<float4*>(g_hsum)[i] = z;
    else if (i < NN * 16 + NN / 4) reinterpret_cast<float4*>(g_deg)[i - NN * 16] = z;
}

// ================= K1: g_nm = x @ [W1a | W1b] (+b1 on first half) =================
// As[128][68] tf32, Ws[64][136] tf32
#define K1_SMEM ((128 * 68 + 64 * 136) * 4)
__global__ __launch_bounds__(256, 2)
void k1_kernel(const float* __restrict__ x, const float* __restrict__ W1,
               const float* __restrict__ b1, int M) {
    extern __shared__ float sm[];
    uint32_t* As = reinterpret_cast<uint32_t*>(sm);
    uint32_t* Ws = As + 128 * 68;
    const int tid = threadIdx.x, lane = tid & 31, wid = tid >> 5;
    const int g = lane >> 2, tg = lane & 3;
    const int m0 = blockIdx.x * 128;

    {   // x tile: 2 threads per row
        int r = tid >> 1, h = (tid & 1) * 32;
        bool v = (m0 + r) < M;
        const float4* xr = reinterpret_cast<const float4*>(x + (size_t)(m0 + r) * 64 + h);
        uint32_t* dst = As + r * 68 + h;
        #pragma unroll
        for (int q = 0; q < 8; q++) {
            float4 val = v ? __ldg(xr + q) : make_float4(0.f, 0.f, 0.f, 0.f);
            uint4 u; u.x = f2tf32(val.x); u.y = f2tf32(val.y); u.z = f2tf32(val.z); u.w = f2tf32(val.w);
            *reinterpret_cast<uint4*>(dst + 4 * q) = u;
        }
    }
    for (int idx = tid; idx < 64 * 128; idx += 256) {
        int k = idx >> 7, n = idx & 127;
        float w = (n < 64) ? W1[k * 64 + n] : W1[(64 + k) * 64 + (n - 64)];
        Ws[k * 136 + n] = f2tf32(w);
    }
    __syncthreads();

    const int rb = wid * 16;
    float acc[16][4];
    #pragma unroll
    for (int nt = 0; nt < 16; nt++) acc[nt][0] = acc[nt][1] = acc[nt][2] = acc[nt][3] = 0.f;

    #pragma unroll
    for (int kt = 0; kt < 8; kt++) {
        const int k0 = kt * 8;
        uint32_t a0 = As[(rb + g) * 68 + k0 + tg];
        uint32_t a1 = As[(rb + g + 8) * 68 + k0 + tg];
        uint32_t a2 = As[(rb + g) * 68 + k0 + tg + 4];
        uint32_t a3 = As[(rb + g + 8) * 68 + k0 + tg + 4];
        #pragma unroll
        for (int nt = 0; nt < 16; nt++) {
            uint32_t b0 = Ws[(k0 + tg) * 136 + 8 * nt + g];
            uint32_t b1v = Ws[(k0 + tg + 4) * 136 + 8 * nt + g];
            mma_tf32(acc[nt], a0, a1, a2, a3, b0, b1v);
        }
    }
    const int r0 = m0 + rb + g, r1 = r0 + 8;
    #pragma unroll
    for (int nt = 0; nt < 16; nt++) {
        const int col = 8 * nt + 2 * tg;
        float e0 = 0.f, e1 = 0.f;
        if (col < 64) { e0 = __ldg(b1 + col); e1 = __ldg(b1 + col + 1); }
        if (r0 < M) *reinterpret_cast<float2*>(g_nm + (size_t)r0 * 128 + col)
                        = make_float2(acc[nt][0] + e0, acc[nt][1] + e1);
        if (r1 < M) *reinterpret_cast<float2*>(g_nm + (size_t)r1 * 128 + col)
                        = make_float2(acc[nt][2] + e0, acc[nt][3] + e1);
    }
}

// ================= K2: per-edge h = relu(pre[src]+post[dst]+ea@W1e) -> scatter =================
// words: Aea[128*20] | Wes[16*136] | Acc[128*68] | Ssrc[128] | Sdst[128]
#define AEA_O  0
#define WES_O  (128 * 20)
#define ACC_O  (WES_O + 16 * 136)
#define SSRC_O (ACC_O + 128 * 68)
#define SDST_O (SSRC_O + 128)
#define K2_SMEM ((SDST_O + 128) * 4)   // 54784 B
__global__ __launch_bounds__(256)
void k2_kernel(const int* __restrict__ ei, const float* __restrict__ ea,
               const float* __restrict__ W1, int E) {
    extern __shared__ float sm[];
    uint32_t* Aea = reinterpret_cast<uint32_t*>(sm) + AEA_O;
    uint32_t* Wes = reinterpret_cast<uint32_t*>(sm) + WES_O;
    float*    Acc = sm + ACC_O;
    int*      Ssrc = reinterpret_cast<int*>(sm) + SSRC_O;
    int*      Sdst = reinterpret_cast<int*>(sm) + SDST_O;

    const int tid = threadIdx.x, lane = tid & 31, wid = tid >> 5;
    const int g = lane >> 2, tg = lane & 3;
    const int e0 = blockIdx.x * 128;

    if (tid < 128) {
        int e = e0 + tid;
        Ssrc[tid] = (e < E) ? ei[e] : 0;
        Sdst[tid] = (e < E) ? ei[E + e] : 0;
    }
    #pragma unroll
    for (int p = 0; p < 2; p++) {
        int q = tid + 256 * p;            // 0..511
        int r = q >> 2, c = (q & 3) * 4;
        int e = e0 + r;
        float4 v = (e < E) ? __ldg(reinterpret_cast<const float4*>(ea + (size_t)e * 16 + c))
                           : make_float4(0.f, 0.f, 0.f, 0.f);
        uint4 u; u.x = f2tf32(v.x); u.y = f2tf32(v.y); u.z = f2tf32(v.z); u.w = f2tf32(v.w);
        *reinterpret_cast<uint4*>(Aea + r * 20 + c) = u;
    }
    for (int idx = tid; idx < 16 * 64; idx += 256) {
        int k = idx >> 6, n = idx & 63;
        Wes[k * 136 + n] = f2tf32(W1[(128 + k) * 64 + n]);
    }
    __syncthreads();

    // tiny MMA: acc = ea[128x16] @ W1e[16x64]
    const int rb = wid * 16;
    float acc[8][4];
    #pragma unroll
    for (int nt = 0; nt < 8; nt++) acc[nt][0] = acc[nt][1] = acc[nt][2] = acc[nt][3] = 0.f;
    #pragma unroll
    for (int kt = 0; kt < 2; kt++) {
        const int k0 = kt * 8;
        uint32_t a0 = Aea[(rb + g) * 20 + k0 + tg];
        uint32_t a1 = Aea[(rb + g + 8) * 20 + k0 + tg];
        uint32_t a2 = Aea[(rb + g) * 20 + k0 + tg + 4];
        uint32_t a3 = Aea[(rb + g + 8) * 20 + k0 + tg + 4];
        #pragma unroll
        for (int nt = 0; nt < 8; nt++) {
            uint32_t b0 = Wes[(k0 + tg) * 136 + 8 * nt + g];
            uint32_t b1v = Wes[(k0 + tg + 4) * 136 + 8 * nt + g];
            mma_tf32(acc[nt], a0, a1, a2, a3, b0, b1v);
        }
    }
    #pragma unroll
    for (int nt = 0; nt < 8; nt++) {
        const int col = 8 * nt + 2 * tg;
        *reinterpret_cast<float2*>(Acc + (rb + g) * 68 + col)     = make_float2(acc[nt][0], acc[nt][1]);
        *reinterpret_cast<float2*>(Acc + (rb + g + 8) * 68 + col) = make_float2(acc[nt][2], acc[nt][3]);
    }
    __syncthreads();

    // pass 2: row-coalesced gather + relu + row-coalesced scatter
    const int rr = tid >> 4;              // 0..15
    const int c4 = (tid & 15) * 4;        // col quad
    #pragma unroll
    for (int p = 0; p < 8; p++) {
        const int r = p * 16 + rr;
        const int e = e0 + r;
        if (e < E) {
            const int src = Ssrc[r], dst = Sdst[r];
            float4 pre  = __ldg(reinterpret_cast<const float4*>(g_nm + (size_t)src * 128 + c4));
            float4 post = __ldg(reinterpret_cast<const float4*>(g_nm + (size_t)dst * 128 + 64 + c4));
            float4 a = *reinterpret_cast<const float4*>(Acc + r * 68 + c4);
            float hx = fmaxf(pre.x + post.x + a.x, 0.f);
            float hy = fmaxf(pre.y + post.y + a.y, 0.f);
            float hz = fmaxf(pre.z + post.z + a.z, 0.f);
            float hw = fmaxf(pre.w + post.w + a.w, 0.f);
            red_add_v4(g_hsum + (size_t)dst * 64 + c4, hx, hy, hz, hw);
            if ((tid & 15) == 0) red_add_f32(g_deg + dst, 1.0f);
        }
    }
}

// ================= K3: out = g_hsum @ W2 + deg (x) b2 =================
#define K3_SMEM ((128 * 68 + 64 * 72) * 4)
__global__ __launch_bounds__(256, 2)
void k3_kernel(const float* __restrict__ W2, const float* __restrict__ b2,
               float* __restrict__ out, int M) {
    extern __shared__ float sm[];
    uint32_t* As = reinterpret_cast<uint32_t*>(sm);
    uint32_t* Ws = As + 128 * 68;
    const int tid = threadIdx.x, lane = tid & 31, wid = tid >> 5;
    const int g = lane >> 2, tg = lane & 3;
    const int m0 = blockIdx.x * 128;

    {
        int r = tid >> 1, h = (tid & 1) * 32;
        bool v = (m0 + r) < M;
        const float4* xr = reinterpret_cast<const float4*>(g_hsum + (size_t)(m0 + r) * 64 + h);
        uint32_t* dst = As + r * 68 + h;
        #pragma unroll
        for (int q = 0; q < 8; q++) {
            float4 val = v ? *(xr + q) : make_float4(0.f, 0.f, 0.f, 0.f);
            uint4 u; u.x = f2tf32(val.x); u.y = f2tf32(val.y); u.z = f2tf32(val.z); u.w = f2tf32(val.w);
            *reinterpret_cast<uint4*>(dst + 4 * q) = u;
        }
    }
    for (int idx = tid; idx < 64 * 64; idx += 256) {
        int k = idx >> 6, n = idx & 63;
        Ws[k * 72 + n] = f2tf32(W2[idx]);
    }
    __syncthreads();

    const int rb = wid * 16;
    float acc[8][4];
    #pragma unroll
    for (int nt = 0; nt < 8; nt++) acc[nt][0] = acc[nt][1] = acc[nt][2] = acc[nt][3] = 0.f;
    #pragma unroll
    for (int kt = 0; kt < 8; kt++) {
        const int k0 = kt * 8;
        uint32_t a0 = As[(rb + g) * 68 + k0 + tg];
        uint32_t a1 = As[(rb + g + 8) * 68 + k0 + tg];
        uint32_t a2 = As[(rb + g) * 68 + k0 + tg + 4];
        uint32_t a3 = As[(rb + g + 8) * 68 + k0 + tg + 4];
        #pragma unroll
        for (int nt = 0; nt < 8; nt++) {
            uint32_t b0 = Ws[(k0 + tg) * 72 + 8 * nt + g];
            uint32_t b1v = Ws[(k0 + tg + 4) * 72 + 8 * nt + g];
            mma_tf32(acc[nt], a0, a1, a2, a3, b0, b1v);
        }
    }
    const int r0 = m0 + rb + g, r1 = r0 + 8;
    const float d0 = (r0 < M) ? g_deg[r0] : 0.f;
    const float d1 = (r1 < M) ? g_deg[r1] : 0.f;
    #pragma unroll
    for (int nt = 0; nt < 8; nt++) {
        const int col = 8 * nt + 2 * tg;
        const float bb0 = __ldg(b2 + col), bb1 = __ldg(b2 + col + 1);
        if (r0 < M) *reinterpret_cast<float2*>(out + (size_t)r0 * 64 + col)
                        = make_float2(acc[nt][0] + d0 * bb0, acc[nt][1] + d0 * bb1);
        if (r1 < M) *reinterpret_cast<float2*>(out + (size_t)r1 * 64 + col)
                        = make_float2(acc[nt][2] + d1 * bb0, acc[nt][3] + d1 * bb1);
    }
}

// ---------------- launch ----------------
extern "C" void kernel_launch(void* const* d_in, const int* in_sizes, int n_in,
                              void* d_out, int out_size) {
    const float* x  = (const float*)d_in[0];
    const int*   ei = (const int*)d_in[1];      // int32 (JAX x64 disabled)
    const float* ea = (const float*)d_in[2];
    const float* W1 = (const float*)d_in[3];
    const float* b1 = (const float*)d_in[4];
    const float* W2 = (const float*)d_in[5];
    const float* b2 = (const float*)d_in[6];
    float* out = (float*)d_out;

    int E = in_sizes[1] / 2;
    int M = out_size / 64;                      // number of nodes
    int mtiles = (M + 127) / 128;
    int etiles = (E + 127) / 128;

    cudaFuncSetAttribute(k1_kernel, cudaFuncAttributeMaxDynamicSharedMemorySize, K1_SMEM);
    cudaFuncSetAttribute(k2_kernel, cudaFuncAttributeMaxDynamicSharedMemorySize, K2_SMEM);
    cudaFuncSetAttribute(k3_kernel, cudaFuncAttributeMaxDynamicSharedMemorySize, K3_SMEM);

    int zn = NN * 16 + NN / 4;
    zero_kernel<<<(zn + 255) / 256, 256>>>();
    k1_kernel<<<mtiles, 256, K1_SMEM>>>(x, W1, b1, M);
    k2_kernel<<<etiles, 256, K2_SMEM>>>(ei, ea, W1, E);
    k3_kernel<<<mtiles, 256, K3_SMEM>>>(W2, b2, out, M);
}